// round 6
// baseline (speedup 1.0000x reference)
#include <cuda_runtime.h>
#include <cuda_bf16.h>

// ---------------------------------------------------------------------------
// GAT 2-layer: h1 = GAT(X, W0, al0, ar0, b0); out = GAT(h1, W1, al1, ar1, b1)
// N = 100000 nodes, E = 1,700,000 edges (incl. self loops), d: 1433 -> 140 -> 7
// ---------------------------------------------------------------------------

#define MAXN 100000
#define MAXE 1700000
#define D_IN 1433
#define D_H  140
#define D_O  7

__device__ float g_h0[(size_t)MAXN * D_H];   // layer0 projection X@W0
__device__ float g_h1[(size_t)MAXN * D_H];   // layer0 output (post agg+relu)
__device__ float g_h1p[(size_t)MAXN * D_O];  // layer1 projection h1@W1
__device__ float g_el0[MAXN], g_er0[MAXN];
__device__ float g_el1[MAXN], g_er1[MAXN];
__device__ int   g_deg[MAXN];
__device__ int   g_offs[MAXN + 1];
__device__ int   g_cursor[MAXN];
__device__ int   g_ssrc[MAXE];
__device__ int   g_partials[128];

// ---------------- packed fp32x2 helpers (sm_103a double-rate FFMA) ---------
__device__ __forceinline__ unsigned long long pack2(float x, float y) {
    unsigned long long r;
    asm("mov.b64 %0, {%1, %2};" : "=l"(r) : "f"(x), "f"(y));
    return r;
}
__device__ __forceinline__ void unpack2(unsigned long long v, float& x, float& y) {
    asm("mov.b64 {%0, %1}, %2;" : "=f"(x), "=f"(y) : "l"(v));
}
__device__ __forceinline__ unsigned long long ffma2(unsigned long long a,
                                                    unsigned long long b,
                                                    unsigned long long c) {
    unsigned long long d;
    asm("fma.rn.f32x2 %0, %1, %2, %3;" : "=l"(d) : "l"(a), "l"(b), "l"(c));
    return d;
}

// ---------------- cp.async helpers -----------------------------------------
__device__ __forceinline__ void cp_async4(void* smem, const void* g) {
    unsigned sa = (unsigned)__cvta_generic_to_shared(smem);
    asm volatile("cp.async.ca.shared.global [%0], [%1], 4;\n" :: "r"(sa), "l"(g));
}
__device__ __forceinline__ void cp_async16(void* smem, const void* g) {
    unsigned sa = (unsigned)__cvta_generic_to_shared(smem);
    asm volatile("cp.async.ca.shared.global [%0], [%1], 16;\n" :: "r"(sa), "l"(g));
}
__device__ __forceinline__ void cp_commit() {
    asm volatile("cp.async.commit_group;\n");
}
__device__ __forceinline__ void cp_wait_all() {
    asm volatile("cp.async.wait_group 0;\n");
}

// ===========================================================================
// GEMM0: g_h0 = X @ W0.  BM=128, BN=144 (covers 140), BK=16, 256 threads.
// Thread (tx = tid&31, ty = tid>>5): rows tx + 32r (r<4), cols ty*18 + 2j (j<9)
// Accumulators live as f32x2 pairs -> 36 FFMA2 per k-step per thread.
// ===========================================================================
#define GM_BM 128
#define GM_BN 144
#define GM_BK 16

__global__ __launch_bounds__(256, 2)
void gemm0_kernel(const float* __restrict__ X, const float* __restrict__ W, int M)
{
    const int K = D_IN, N = D_H;
    __shared__ __align__(16) float As[2][GM_BM][GM_BK + 1];  // [m][k], pad 17
    __shared__ __align__(16) float Bs[2][GM_BK][GM_BN];      // [k][n]

    const int tid = threadIdx.x;
    const int tx = tid & 31, ty = tid >> 5;
    const int m0 = blockIdx.x * GM_BM;

    // zero the N-pad columns (140..143) of both stages once
    for (int i = tid; i < 2 * GM_BK * 4; i += 256) {
        int s  = i / (GM_BK * 4);
        int rm = i % (GM_BK * 4);
        Bs[s][rm >> 2][D_H + (rm & 3)] = 0.f;
    }

    auto load_stage = [&](int s, int kc) {
        const int k0 = kc * GM_BK;
        // A tile: 128 x 16 floats (X rows are only 4B-aligned -> 4B cp.async)
        #pragma unroll
        for (int q = tid; q < GM_BM * GM_BK; q += 256) {
            int row = q >> 4, col = q & 15;
            int m = m0 + row, k = k0 + col;
            float* dp = &As[s][row][col];
            if (m < M && k < K) cp_async4(dp, X + (size_t)m * K + k);
            else                *dp = 0.f;
        }
        // B tile: 16 x 140 floats as 16 x 35 float4 (W row stride 560B, 16B-aligned)
        for (int q = tid; q < GM_BK * 35; q += 256) {
            int row = q / 35, c4 = q % 35;
            int k = k0 + row;
            float* dp = &Bs[s][row][c4 * 4];
            if (k < K) cp_async16(dp, W + (size_t)k * N + c4 * 4);
            else { dp[0] = 0.f; dp[1] = 0.f; dp[2] = 0.f; dp[3] = 0.f; }
        }
    };

    unsigned long long acc[4][9];
    #pragma unroll
    for (int r = 0; r < 4; ++r)
        #pragma unroll
        for (int j = 0; j < 9; ++j) acc[r][j] = 0ull;

    const int NC = (K + GM_BK - 1) / GM_BK;  // 90
    load_stage(0, 0);
    cp_commit();

    for (int kc = 0; kc < NC; ++kc) {
        cp_wait_all();
        __syncthreads();
        const int buf = kc & 1;
        if (kc + 1 < NC) { load_stage(buf ^ 1, kc + 1); cp_commit(); }

        #pragma unroll
        for (int k = 0; k < GM_BK; ++k) {
            unsigned long long a2[4];
            #pragma unroll
            for (int r = 0; r < 4; ++r) {
                float av = As[buf][tx + 32 * r][k];   // lane stride 17 floats: conflict-free
                a2[r] = pack2(av, av);
            }
            unsigned long long b2[9];
            #pragma unroll
            for (int j = 0; j < 9; ++j)               // warp-uniform: smem broadcast
                b2[j] = *(const unsigned long long*)&Bs[buf][k][ty * 18 + 2 * j];
            #pragma unroll
            for (int r = 0; r < 4; ++r)
                #pragma unroll
                for (int j = 0; j < 9; ++j)
                    acc[r][j] = ffma2(a2[r], b2[j], acc[r][j]);
        }
        __syncthreads();
    }

    // epilogue: store valid (m, n) outputs
    #pragma unroll
    for (int r = 0; r < 4; ++r) {
        int m = m0 + tx + 32 * r;
        if (m >= M) continue;
        float* orow = g_h0 + (size_t)m * D_H;
        #pragma unroll
        for (int j = 0; j < 9; ++j) {
            int nn = ty * 18 + 2 * j;
            float lo, hi;
            unpack2(acc[r][j], lo, hi);
            if (nn     < D_H) orow[nn]     = lo;
            if (nn + 1 < D_H) orow[nn + 1] = hi;
        }
    }
}

// ===========================================================================
// el/er for layer 0: warp per node, el[i] = h0[i].al, er[i] = h0[i].ar
// ===========================================================================
__global__ void elr_kernel(const float* __restrict__ h, const float* __restrict__ al,
                           const float* __restrict__ ar, float* __restrict__ el,
                           float* __restrict__ er, int n)
{
    int w = (blockIdx.x * blockDim.x + threadIdx.x) >> 5;
    int lane = threadIdx.x & 31;
    if (w >= n) return;
    const float* hr = h + (size_t)w * D_H;
    float sl = 0.f, sr = 0.f;
    #pragma unroll
    for (int u = 0; u < 5; ++u) {
        int c = lane + 32 * u;
        if (c < D_H) { float hv = hr[c]; sl += hv * al[c]; sr += hv * ar[c]; }
    }
    for (int o = 16; o; o >>= 1) {
        sl += __shfl_xor_sync(0xffffffffu, sl, o);
        sr += __shfl_xor_sync(0xffffffffu, sr, o);
    }
    if (lane == 0) { el[w] = sl; er[w] = sr; }
}

// ===========================================================================
// CSR build: count -> 3-phase exclusive scan -> scatter
// ===========================================================================
__global__ void zero_deg_kernel(int n) {
    int i = blockIdx.x * blockDim.x + threadIdx.x;
    if (i < n) g_deg[i] = 0;
}
__global__ void count_kernel(const int* __restrict__ dst, int e) {
    int i = blockIdx.x * blockDim.x + threadIdx.x;
    if (i < e) atomicAdd(&g_deg[dst[i]], 1);
}
__global__ void scan_chunk_sums_kernel(int n) {
    int b = blockIdx.x, t = threadIdx.x;
    int base = b * 1024 + t * 4;
    int s = 0;
    #pragma unroll
    for (int i = 0; i < 4; ++i) { int idx = base + i; if (idx < n) s += g_deg[idx]; }
    __shared__ int wsum[8];
    for (int o = 16; o; o >>= 1) s += __shfl_xor_sync(0xffffffffu, s, o);
    if ((t & 31) == 0) wsum[t >> 5] = s;
    __syncthreads();
    if (t == 0) {
        int tot = 0;
        #pragma unroll
        for (int i = 0; i < 8; ++i) tot += wsum[i];
        g_partials[b] = tot;
    }
}
__global__ void scan_partials_kernel(int nch, int n, int e) {
    if (threadIdx.x == 0) {
        int acc = 0;
        for (int i = 0; i < nch; ++i) { int v = g_partials[i]; g_partials[i] = acc; acc += v; }
        g_offs[n] = e;
    }
}
__global__ void scan_final_kernel(int n) {
    int b = blockIdx.x, t = threadIdx.x;
    int base = b * 1024 + t * 4;
    int v[4]; int s = 0;
    #pragma unroll
    for (int i = 0; i < 4; ++i) { int idx = base + i; v[i] = (idx < n) ? g_deg[idx] : 0; s += v[i]; }
    __shared__ int wsum[8];
    int lane = t & 31, wid = t >> 5;
    int inc = s;
    for (int o = 1; o < 32; o <<= 1) {
        int tv = __shfl_up_sync(0xffffffffu, inc, o);
        if (lane >= o) inc += tv;
    }
    if (lane == 31) wsum[wid] = inc;
    __syncthreads();
    int woff = 0;
    for (int i = 0; i < wid; ++i) woff += wsum[i];
    int ex = woff + inc - s + g_partials[b];
    #pragma unroll
    for (int i = 0; i < 4; ++i) {
        int idx = base + i;
        if (idx < n) { g_offs[idx] = ex; g_cursor[idx] = ex; ex += v[i]; }
    }
}
__global__ void fill_kernel(const int* __restrict__ src, const int* __restrict__ dst, int e) {
    int i = blockIdx.x * blockDim.x + threadIdx.x;
    if (i < e) { int p = atomicAdd(&g_cursor[dst[i]], 1); g_ssrc[p] = src[i]; }
}

// ===========================================================================
// Aggregation: warp per dst node. Online softmax over incoming edges, then
// weighted gather of h[src] rows -> relu(acc + bias). No global atomics.
// ===========================================================================
template<int D, int NU>
__global__ void aggregate_kernel(const float* __restrict__ h,
                                 const float* __restrict__ el,
                                 const float* __restrict__ er,
                                 const float* __restrict__ bias,
                                 float* __restrict__ out, int n)
{
    int w = (blockIdx.x * blockDim.x + threadIdx.x) >> 5;
    int lane = threadIdx.x & 31;
    if (w >= n) return;
    const int start = g_offs[w], end = g_offs[w + 1];
    const float er_i = er[w];

    // pass 1: online softmax (m, s) per lane across its edges
    float m = -1e30f, s = 0.f;
    for (int e = start + lane; e < end; e += 32) {
        int sj = g_ssrc[e];
        float v = el[sj] + er_i;
        v = (v > 0.f) ? v : 0.2f * v;
        float nm = fmaxf(m, v);
        s = s * __expf(m - nm) + __expf(v - nm);
        m = nm;
    }
    // warp merge
    for (int o = 16; o; o >>= 1) {
        float om = __shfl_xor_sync(0xffffffffu, m, o);
        float os = __shfl_xor_sync(0xffffffffu, s, o);
        float nm = fmaxf(m, om);
        s = s * __expf(m - nm) + os * __expf(om - nm);
        m = nm;
    }
    const float inv = 1.f / s;

    // pass 2: accumulate a_e * h[src]
    float acc[NU];
    #pragma unroll
    for (int u = 0; u < NU; ++u) acc[u] = 0.f;

    for (int e0 = start; e0 < end; e0 += 32) {
        int e = e0 + lane;
        int sj = 0; float a = 0.f;
        if (e < end) {
            sj = g_ssrc[e];
            float v = el[sj] + er_i;
            v = (v > 0.f) ? v : 0.2f * v;
            a = __expf(v - m) * inv;
        }
        int cnt = min(32, end - e0);
        for (int j = 0; j < cnt; ++j) {
            int   sje = __shfl_sync(0xffffffffu, sj, j);
            float aje = __shfl_sync(0xffffffffu, a, j);
            const float* hr = h + (size_t)sje * D;
            #pragma unroll
            for (int u = 0; u < NU; ++u) {
                int c = lane + 32 * u;
                if (c < D) acc[u] += aje * hr[c];
            }
        }
    }

    #pragma unroll
    for (int u = 0; u < NU; ++u) {
        int c = lane + 32 * u;
        if (c < D) out[(size_t)w * D + c] = fmaxf(acc[u] + bias[c], 0.f);
    }
}

// ===========================================================================
// Layer-1 projection: h1p = h1 @ W1 (140 -> 7), plus el1/er1. Warp per node.
// W1 stored transposed in smem so lane-strided reads are conflict-free.
// ===========================================================================
__global__ void proj1_kernel(const float* __restrict__ h1, const float* __restrict__ W1,
                             const float* __restrict__ al1, const float* __restrict__ ar1,
                             float* __restrict__ h1p, float* __restrict__ el1,
                             float* __restrict__ er1, int n)
{
    __shared__ float Wt[D_O * D_H];  // [j][c]
    __shared__ float als[D_O], ars[D_O];
    for (int i = threadIdx.x; i < D_H * D_O; i += blockDim.x) {
        int c = i / D_O, j = i % D_O;
        Wt[j * D_H + c] = W1[i];
    }
    if (threadIdx.x < D_O) { als[threadIdx.x] = al1[threadIdx.x]; ars[threadIdx.x] = ar1[threadIdx.x]; }
    __syncthreads();

    int w = (blockIdx.x * blockDim.x + threadIdx.x) >> 5;
    int lane = threadIdx.x & 31;
    if (w >= n) return;

    float p[D_O];
    #pragma unroll
    for (int j = 0; j < D_O; ++j) p[j] = 0.f;

    const float* hr = h1 + (size_t)w * D_H;
    for (int c = lane; c < D_H; c += 32) {
        float hc = hr[c];
        #pragma unroll
        for (int j = 0; j < D_O; ++j) p[j] += hc * Wt[j * D_H + c];
    }
    #pragma unroll
    for (int j = 0; j < D_O; ++j)
        for (int o = 16; o; o >>= 1) p[j] += __shfl_xor_sync(0xffffffffu, p[j], o);

    if (lane == 0) {
        float elv = 0.f, erv = 0.f;
        float* op = h1p + (size_t)w * D_O;
        #pragma unroll
        for (int j = 0; j < D_O; ++j) {
            op[j] = p[j];
            elv += p[j] * als[j];
            erv += p[j] * ars[j];
        }
        el1[w] = elv;
        er1[w] = erv;
    }
}

// ===========================================================================
// launch
// ===========================================================================
extern "C" void kernel_launch(void* const* d_in, const int* in_sizes, int n_in,
                              void* d_out, int out_size)
{
    // --- resolve inputs by element count (robust to metadata permutations;
    //     preserves in-group order which matches the setup dict) -------------
    const float* X = nullptr;  const int* src = nullptr; const int* dst = nullptr;
    const float* W0 = nullptr; const float* al0 = nullptr; const float* ar0 = nullptr;
    const float* b0 = nullptr; const float* W1 = nullptr; const float* al1 = nullptr;
    const float* ar1 = nullptr; const float* b1 = nullptr;

    for (int i = 0; i < n_in; ++i) {
        long long s = in_sizes[i];
        void* p = d_in[i];
        if      (s == (long long)MAXN * D_IN) X  = (const float*)p;
        else if (s == (long long)MAXE) { if (!src) src = (const int*)p; else dst = (const int*)p; }
        else if (s == (long long)D_IN * D_H) W0 = (const float*)p;
        else if (s == (long long)D_H * D_O)  W1 = (const float*)p;
        else if (s == D_H) { if (!al0) al0 = (const float*)p; else if (!ar0) ar0 = (const float*)p; else b0 = (const float*)p; }
        else if (s == D_O) { if (!al1) al1 = (const float*)p; else if (!ar1) ar1 = (const float*)p; else b1 = (const float*)p; }
    }
    // positional fallback (dict order) if anything unresolved
    if (!X || !src || !dst || !W0 || !al0 || !ar0 || !b0 || !W1 || !al1 || !ar1 || !b1) {
        X   = (const float*)d_in[0];  src = (const int*)d_in[1];  dst = (const int*)d_in[2];
        W0  = (const float*)d_in[3];  al0 = (const float*)d_in[4]; ar0 = (const float*)d_in[5];
        b0  = (const float*)d_in[6];  W1  = (const float*)d_in[7]; al1 = (const float*)d_in[8];
        ar1 = (const float*)d_in[9];  b1  = (const float*)d_in[10];
    }
    float* out = (float*)d_out;

    // --- FIX (R5 root cause): __device__ symbols evaluated in host code are
    //     host-shadow addresses, NOT device pointers. Resolve properly. ------
    float *h0, *h1, *h1p, *el0, *er0, *el1, *er1;
    cudaGetSymbolAddress((void**)&h0,  g_h0);
    cudaGetSymbolAddress((void**)&h1,  g_h1);
    cudaGetSymbolAddress((void**)&h1p, g_h1p);
    cudaGetSymbolAddress((void**)&el0, g_el0);
    cudaGetSymbolAddress((void**)&er0, g_er0);
    cudaGetSymbolAddress((void**)&el1, g_el1);
    cudaGetSymbolAddress((void**)&er1, g_er1);

    const int n = (int)(143300000LL / D_IN) == 100000 && in_sizes ? 0 : 0; // (no-op; keep simple)
    const int N = [&]{ // node count from X size
        for (int i = 0; i < n_in; ++i) if (in_sizes[i] % D_IN == 0 && in_sizes[i] > 1000000) return in_sizes[i] / D_IN;
        return MAXN; }();
    int E = MAXE;
    { // edge count = size of src array
        for (int i = 0; i < n_in; ++i) if ((const void*)d_in[i] == (const void*)src) { E = in_sizes[i]; break; }
    }
    (void)n;

    const int TB = 256;
    const int nwarp_blocks = (N + 7) / 8;        // 8 warps per 256-thread block
    const int nch = (N + 1023) / 1024;

    // --- CSR build (by dst) ---
    zero_deg_kernel<<<(N + TB - 1) / TB, TB>>>(N);
    count_kernel<<<(E + TB - 1) / TB, TB>>>(dst, E);
    scan_chunk_sums_kernel<<<nch, TB>>>(N);
    scan_partials_kernel<<<1, 32>>>(nch, N, E);
    scan_final_kernel<<<nch, TB>>>(N);
    fill_kernel<<<(E + TB - 1) / TB, TB>>>(src, dst, E);

    // --- layer 0 ---
    gemm0_kernel<<<(N + GM_BM - 1) / GM_BM, 256>>>(X, W0, N);
    elr_kernel<<<nwarp_blocks, TB>>>(h0, al0, ar0, el0, er0, N);
    aggregate_kernel<D_H, 5><<<nwarp_blocks, TB>>>(h0, el0, er0, b0, h1, N);

    // --- layer 1 ---
    proj1_kernel<<<nwarp_blocks, TB>>>(h1, W1, al1, ar1, h1p, el1, er1, N);
    aggregate_kernel<D_O, 1><<<nwarp_blocks, TB>>>(h1p, el1, er1, b1, out, N);
}

// round 9
// speedup vs baseline: 1.7303x; 1.7303x over previous
#include <cuda_runtime.h>
#include <cuda_bf16.h>
#include <cstdint>

// ---------------------------------------------------------------------------
// GAT 2-layer. Layer-0 projection on HMMA (mma.sync bf16, 3-term split).
// N = 100000 nodes, E = 1,700,000 edges, dims 1433 -> 140 -> 7
// NOTE: harness compiles PTX at compute_103 (no 'a') -> tcgen05 unavailable;
// mma.sync/ldmatrix are family-common and compile.
// ---------------------------------------------------------------------------

#define MAXN 100000
#define MAXE 1700000
#define D_IN 1433
#define D_H  140
#define D_O  7

#define NCHUNKS 23            // 23*64 = 1472 >= 1433
#define KPAD    (NCHUNKS * 64)
#define NPAD    144
#define PITCH   72            // bf16 elems per smem row (144B: ldmatrix conflict-free)
#define SA      (128 * PITCH) // 9216 elems, A image per buffer
#define SB      (NPAD * PITCH)// 10368 elems, B image per buffer
#define AHI_OFF(b) ((b) * SA)
#define ALO_OFF(b) (2 * SA + (b) * SA)
#define BHI_OFF(b) (4 * SA + (b) * SB)
#define BLO_OFF(b) (4 * SA + 2 * SB + (b) * SB)
#define SM_ELEMS   (4 * SA + 4 * SB)            // 78336
#define SM_BYTES   (SM_ELEMS * 2)               // 156672

__device__ float g_h0[(size_t)MAXN * D_H];
__device__ float g_h1[(size_t)MAXN * D_H];
__device__ float g_h1p[(size_t)MAXN * D_O];
__device__ float g_el0[MAXN], g_er0[MAXN];
__device__ float g_el1[MAXN], g_er1[MAXN];
__device__ int   g_deg[MAXN];
__device__ int   g_offs[MAXN + 1];
__device__ int   g_cursor[MAXN];
__device__ int   g_ssrc[MAXE];
__device__ int   g_partials[128];
__device__ __nv_bfloat16 g_Bhi[(size_t)NPAD * KPAD];   // W0^T hi image [n][k]
__device__ __nv_bfloat16 g_Blo[(size_t)NPAD * KPAD];   // W0^T lo image

// ---------------- helpers ---------------------------------------------------
__device__ __forceinline__ uint32_t smem_u32(const void* p) {
    return (uint32_t)__cvta_generic_to_shared(p);
}
__device__ __forceinline__ void cp_async16(void* smem, const void* g) {
    asm volatile("cp.async.ca.shared.global [%0], [%1], 16;\n"
                 :: "r"(smem_u32(smem)), "l"(g));
}
__device__ __forceinline__ void cp_commit()   { asm volatile("cp.async.commit_group;\n"); }
__device__ __forceinline__ void cp_wait_all() { asm volatile("cp.async.wait_group 0;\n"); }

__device__ __forceinline__ void ldmx4(uint32_t* r, uint32_t addr) {
    asm volatile("ldmatrix.sync.aligned.m8n8.x4.shared.b16 {%0,%1,%2,%3}, [%4];"
        : "=r"(r[0]), "=r"(r[1]), "=r"(r[2]), "=r"(r[3]) : "r"(addr));
}
__device__ __forceinline__ void ldmx2(uint32_t* r, uint32_t addr) {
    asm volatile("ldmatrix.sync.aligned.m8n8.x2.shared.b16 {%0,%1}, [%2];"
        : "=r"(r[0]), "=r"(r[1]) : "r"(addr));
}
__device__ __forceinline__ void mma_bf16(float* d, const uint32_t* a, const uint32_t* b) {
    asm volatile("mma.sync.aligned.m16n8k16.row.col.f32.bf16.bf16.f32 "
        "{%0,%1,%2,%3}, {%4,%5,%6,%7}, {%8,%9}, {%0,%1,%2,%3};"
        : "+f"(d[0]), "+f"(d[1]), "+f"(d[2]), "+f"(d[3])
        : "r"(a[0]), "r"(a[1]), "r"(a[2]), "r"(a[3]), "r"(b[0]), "r"(b[1]));
}

// ===========================================================================
// Prep: W0^T bf16 hi/lo images, K-contiguous rows (mma col-major B layout).
// ===========================================================================
__global__ void prep_b_kernel(const float* __restrict__ W0) {
    int idx = blockIdx.x * blockDim.x + threadIdx.x;
    if (idx >= NPAD * KPAD) return;
    int n = idx / KPAD, k = idx % KPAD;
    float v = (n < D_H && k < D_IN) ? W0[(size_t)k * D_H + n] : 0.f;
    __nv_bfloat16 h = __float2bfloat16(v);
    g_Bhi[idx] = h;
    g_Blo[idx] = __float2bfloat16(v - __bfloat162float(h));
}

// ===========================================================================
// GEMM0: g_h0 = X @ W0 via mma.sync bf16 3-term split.
// CTA: 128 rows x 144 cols, 8 warps (warp = 32 rows x 72 cols), K-chunk 64,
// double-buffered smem; X loaded to regs before MMA section (latency hide).
// ===========================================================================
__global__ __launch_bounds__(256, 1)
void gemm0_mma_kernel(const float* __restrict__ X, int Nn)
{
    extern __shared__ __nv_bfloat16 sm[];
    const int tid  = threadIdx.x;
    const int lane = tid & 31, wid = tid >> 5;
    const int m0   = blockIdx.x * 128;
    const int mW   = (wid >> 1) * 32;     // warp row offset in block
    const int nW   = (wid & 1) * 72;      // warp col offset

    float d[2][9][4];
    #pragma unroll
    for (int t = 0; t < 2; ++t)
        #pragma unroll
        for (int nt = 0; nt < 9; ++nt)
            #pragma unroll
            for (int q = 0; q < 4; ++q) d[t][nt][q] = 0.f;

    float xr[32];

    auto loadB = [&](int c, int buf) {
        #pragma unroll
        for (int q = 0; q < 5; ++q) {
            int idx = tid + q * 256;
            if (idx < NPAD * 8) {
                int n = idx >> 3, j = idx & 7;
                const size_t go = (size_t)n * KPAD + c * 64 + j * 8;
                cp_async16(sm + BHI_OFF(buf) + n * PITCH + j * 8, g_Bhi + go);
                cp_async16(sm + BLO_OFF(buf) + n * PITCH + j * 8, g_Blo + go);
            }
        }
    };
    auto loadX = [&](int c) {
        const int k0 = c * 64;
        #pragma unroll
        for (int j = 0; j < 32; ++j) {
            int i = tid + j * 256;
            int row = i >> 6, col = i & 63;
            int gm = m0 + row, k = k0 + col;
            xr[j] = (gm < Nn && k < D_IN) ? __ldg(X + (size_t)gm * D_IN + k) : 0.f;
        }
    };
    auto storeA = [&](int buf) {
        const bool odd = lane & 1;
        #pragma unroll
        for (int j = 0; j < 32; ++j) {
            int i = tid + j * 256;
            int row = i >> 6, col = i & 63;
            float v  = xr[j];
            float vp = __shfl_xor_sync(0xffffffffu, v, 1);
            float v0 = odd ? vp : v;
            float v1 = odd ? v : vp;
            __nv_bfloat162 h2 = __floats2bfloat162_rn(v0, v1);
            int c0 = col & ~1;
            if (!odd) {
                *(__nv_bfloat162*)(sm + AHI_OFF(buf) + row * PITCH + c0) = h2;
            } else {
                float l0 = v0 - __bfloat162float(h2.x);
                float l1 = v1 - __bfloat162float(h2.y);
                *(__nv_bfloat162*)(sm + ALO_OFF(buf) + row * PITCH + c0) =
                    __floats2bfloat162_rn(l0, l1);
            }
        }
    };
    auto compute = [&](int buf) {
        const uint32_t aH = smem_u32(sm + AHI_OFF(buf));
        const uint32_t aL = smem_u32(sm + ALO_OFF(buf));
        const uint32_t bH = smem_u32(sm + BHI_OFF(buf));
        const uint32_t bL = smem_u32(sm + BLO_OFF(buf));
        #pragma unroll
        for (int ks = 0; ks < 4; ++ks) {
            const int k0 = ks * 16;
            uint32_t ah[2][4], al_[2][4];
            #pragma unroll
            for (int t = 0; t < 2; ++t) {
                uint32_t off = ((mW + t * 16 + (lane & 15)) * PITCH
                                + k0 + (lane >> 4) * 8) * 2;
                ldmx4(ah[t],  aH + off);
                ldmx4(al_[t], aL + off);
            }
            #pragma unroll
            for (int nt = 0; nt < 9; ++nt) {
                uint32_t boff = ((nW + nt * 8 + (lane & 7)) * PITCH
                                 + k0 + ((lane >> 3) & 1) * 8) * 2;
                uint32_t bh[2], bl[2];
                ldmx2(bh, bH + boff);
                ldmx2(bl, bL + boff);
                #pragma unroll
                for (int t = 0; t < 2; ++t) {
                    mma_bf16(d[t][nt], ah[t],  bh);
                    mma_bf16(d[t][nt], al_[t], bh);
                    mma_bf16(d[t][nt], ah[t],  bl);
                }
            }
        }
    };

    // prologue: fill buffer 0
    loadB(0, 0); cp_commit();
    loadX(0); storeA(0);

    for (int c = 0; c < NCHUNKS; ++c) {
        const int buf = c & 1;
        cp_wait_all();
        __syncthreads();
        if (c + 1 < NCHUNKS) { loadB(c + 1, buf ^ 1); cp_commit(); loadX(c + 1); }
        compute(buf);
        if (c + 1 < NCHUNKS) storeA(buf ^ 1);
    }

    // epilogue: C fragment -> g_h0
    #pragma unroll
    for (int t = 0; t < 2; ++t) {
        int mr = m0 + mW + t * 16 + (lane >> 2);
        #pragma unroll
        for (int nt = 0; nt < 9; ++nt) {
            int n = nW + nt * 8 + (lane & 3) * 2;
            if (n < D_H) {
                if (mr < Nn)
                    *(float2*)(g_h0 + (size_t)mr * D_H + n) = make_float2(d[t][nt][0], d[t][nt][1]);
                if (mr + 8 < Nn)
                    *(float2*)(g_h0 + (size_t)(mr + 8) * D_H + n) = make_float2(d[t][nt][2], d[t][nt][3]);
            }
        }
    }
}

// ===========================================================================
// el/er for layer 0
// ===========================================================================
__global__ void elr_kernel(const float* __restrict__ h, const float* __restrict__ al,
                           const float* __restrict__ ar, float* __restrict__ el,
                           float* __restrict__ er, int n)
{
    int w = (blockIdx.x * blockDim.x + threadIdx.x) >> 5;
    int lane = threadIdx.x & 31;
    if (w >= n) return;
    const float* hr = h + (size_t)w * D_H;
    float sl = 0.f, sr = 0.f;
    #pragma unroll
    for (int u = 0; u < 5; ++u) {
        int c = lane + 32 * u;
        if (c < D_H) { float hv = hr[c]; sl += hv * al[c]; sr += hv * ar[c]; }
    }
    for (int o = 16; o; o >>= 1) {
        sl += __shfl_xor_sync(0xffffffffu, sl, o);
        sr += __shfl_xor_sync(0xffffffffu, sr, o);
    }
    if (lane == 0) { el[w] = sl; er[w] = sr; }
}

// ===========================================================================
// CSR build
// ===========================================================================
__global__ void zero_deg_kernel(int n) {
    int i = blockIdx.x * blockDim.x + threadIdx.x;
    if (i < n) g_deg[i] = 0;
}
__global__ void count_kernel(const int* __restrict__ dst, int e) {
    int i = blockIdx.x * blockDim.x + threadIdx.x;
    if (i < e) atomicAdd(&g_deg[dst[i]], 1);
}
__global__ void scan_chunk_sums_kernel(int n) {
    int b = blockIdx.x, t = threadIdx.x;
    int base = b * 1024 + t * 4;
    int s = 0;
    #pragma unroll
    for (int i = 0; i < 4; ++i) { int idx = base + i; if (idx < n) s += g_deg[idx]; }
    __shared__ int wsum[8];
    for (int o = 16; o; o >>= 1) s += __shfl_xor_sync(0xffffffffu, s, o);
    if ((t & 31) == 0) wsum[t >> 5] = s;
    __syncthreads();
    if (t == 0) {
        int tot = 0;
        #pragma unroll
        for (int i = 0; i < 8; ++i) tot += wsum[i];
        g_partials[b] = tot;
    }
}
__global__ void scan_partials_kernel(int nch, int n, int e) {
    if (threadIdx.x == 0) {
        int acc = 0;
        for (int i = 0; i < nch; ++i) { int v = g_partials[i]; g_partials[i] = acc; acc += v; }
        g_offs[n] = e;
    }
}
__global__ void scan_final_kernel(int n) {
    int b = blockIdx.x, t = threadIdx.x;
    int base = b * 1024 + t * 4;
    int v[4]; int s = 0;
    #pragma unroll
    for (int i = 0; i < 4; ++i) { int idx = base + i; v[i] = (idx < n) ? g_deg[idx] : 0; s += v[i]; }
    __shared__ int wsum[8];
    int lane = t & 31, wid = t >> 5;
    int inc = s;
    for (int o = 1; o < 32; o <<= 1) {
        int tv = __shfl_up_sync(0xffffffffu, inc, o);
        if (lane >= o) inc += tv;
    }
    if (lane == 31) wsum[wid] = inc;
    __syncthreads();
    int woff = 0;
    for (int i = 0; i < wid; ++i) woff += wsum[i];
    int ex = woff + inc - s + g_partials[b];
    #pragma unroll
    for (int i = 0; i < 4; ++i) {
        int idx = base + i;
        if (idx < n) { g_offs[idx] = ex; g_cursor[idx] = ex; ex += v[i]; }
    }
}
__global__ void fill_kernel(const int* __restrict__ src, const int* __restrict__ dst, int e) {
    int i = blockIdx.x * blockDim.x + threadIdx.x;
    if (i < e) { int p = atomicAdd(&g_cursor[dst[i]], 1); g_ssrc[p] = src[i]; }
}

// ===========================================================================
// Aggregation: warp per dst node, online softmax + gather, no atomics
// ===========================================================================
template<int D, int NU>
__global__ void aggregate_kernel(const float* __restrict__ h,
                                 const float* __restrict__ el,
                                 const float* __restrict__ er,
                                 const float* __restrict__ bias,
                                 float* __restrict__ out, int n)
{
    int w = (blockIdx.x * blockDim.x + threadIdx.x) >> 5;
    int lane = threadIdx.x & 31;
    if (w >= n) return;
    const int start = g_offs[w], end = g_offs[w + 1];
    const float er_i = er[w];

    float m = -1e30f, s = 0.f;
    for (int e = start + lane; e < end; e += 32) {
        int sj = g_ssrc[e];
        float v = el[sj] + er_i;
        v = (v > 0.f) ? v : 0.2f * v;
        float nm = fmaxf(m, v);
        s = s * __expf(m - nm) + __expf(v - nm);
        m = nm;
    }
    for (int o = 16; o; o >>= 1) {
        float om = __shfl_xor_sync(0xffffffffu, m, o);
        float os = __shfl_xor_sync(0xffffffffu, s, o);
        float nm = fmaxf(m, om);
        s = s * __expf(m - nm) + os * __expf(om - nm);
        m = nm;
    }
    const float inv = 1.f / s;

    float acc[NU];
    #pragma unroll
    for (int u = 0; u < NU; ++u) acc[u] = 0.f;

    for (int e0 = start; e0 < end; e0 += 32) {
        int e = e0 + lane;
        int sj = 0; float a = 0.f;
        if (e < end) {
            sj = g_ssrc[e];
            float v = el[sj] + er_i;
            v = (v > 0.f) ? v : 0.2f * v;
            a = __expf(v - m) * inv;
        }
        int cnt = min(32, end - e0);
        for (int j = 0; j < cnt; ++j) {
            int   sje = __shfl_sync(0xffffffffu, sj, j);
            float aje = __shfl_sync(0xffffffffu, a, j);
            const float* hr = h + (size_t)sje * D;
            #pragma unroll
            for (int u = 0; u < NU; ++u) {
                int c = lane + 32 * u;
                if (c < D) acc[u] += aje * hr[c];
            }
        }
    }

    #pragma unroll
    for (int u = 0; u < NU; ++u) {
        int c = lane + 32 * u;
        if (c < D) out[(size_t)w * D + c] = fmaxf(acc[u] + bias[c], 0.f);
    }
}

// ===========================================================================
// Layer-1 projection (140 -> 7) + el1/er1
// ===========================================================================
__global__ void proj1_kernel(const float* __restrict__ h1, const float* __restrict__ W1,
                             const float* __restrict__ al1, const float* __restrict__ ar1,
                             float* __restrict__ h1p, float* __restrict__ el1,
                             float* __restrict__ er1, int n)
{
    __shared__ float Wt[D_O * D_H];
    __shared__ float als[D_O], ars[D_O];
    for (int i = threadIdx.x; i < D_H * D_O; i += blockDim.x) {
        int c = i / D_O, j = i % D_O;
        Wt[j * D_H + c] = W1[i];
    }
    if (threadIdx.x < D_O) { als[threadIdx.x] = al1[threadIdx.x]; ars[threadIdx.x] = ar1[threadIdx.x]; }
    __syncthreads();

    int w = (blockIdx.x * blockDim.x + threadIdx.x) >> 5;
    int lane = threadIdx.x & 31;
    if (w >= n) return;

    float p[D_O];
    #pragma unroll
    for (int j = 0; j < D_O; ++j) p[j] = 0.f;

    const float* hr = h1 + (size_t)w * D_H;
    for (int c = lane; c < D_H; c += 32) {
        float hc = hr[c];
        #pragma unroll
        for (int j = 0; j < D_O; ++j) p[j] += hc * Wt[j * D_H + c];
    }
    #pragma unroll
    for (int j = 0; j < D_O; ++j)
        for (int o = 16; o; o >>= 1) p[j] += __shfl_xor_sync(0xffffffffu, p[j], o);

    if (lane == 0) {
        float elv = 0.f, erv = 0.f;
        float* op = h1p + (size_t)w * D_O;
        #pragma unroll
        for (int j = 0; j < D_O; ++j) {
            op[j] = p[j];
            elv += p[j] * als[j];
            erv += p[j] * ars[j];
        }
        el1[w] = elv;
        er1[w] = erv;
    }
}

// ===========================================================================
// launch
// ===========================================================================
extern "C" void kernel_launch(void* const* d_in, const int* in_sizes, int n_in,
                              void* d_out, int out_size)
{
    const float* X = nullptr;  const int* src = nullptr; const int* dst = nullptr;
    const float* W0 = nullptr; const float* al0 = nullptr; const float* ar0 = nullptr;
    const float* b0 = nullptr; const float* W1 = nullptr; const float* al1 = nullptr;
    const float* ar1 = nullptr; const float* b1 = nullptr;

    for (int i = 0; i < n_in; ++i) {
        long long s = in_sizes[i];
        void* p = d_in[i];
        if      (s == (long long)MAXN * D_IN) X  = (const float*)p;
        else if (s == (long long)MAXE) { if (!src) src = (const int*)p; else dst = (const int*)p; }
        else if (s == (long long)D_IN * D_H) W0 = (const float*)p;
        else if (s == (long long)D_H * D_O)  W1 = (const float*)p;
        else if (s == D_H) { if (!al0) al0 = (const float*)p; else if (!ar0) ar0 = (const float*)p; else b0 = (const float*)p; }
        else if (s == D_O) { if (!al1) al1 = (const float*)p; else if (!ar1) ar1 = (const float*)p; else b1 = (const float*)p; }
    }
    if (!X || !src || !dst || !W0 || !al0 || !ar0 || !b0 || !W1 || !al1 || !ar1 || !b1) {
        X   = (const float*)d_in[0];  src = (const int*)d_in[1];  dst = (const int*)d_in[2];
        W0  = (const float*)d_in[3];  al0 = (const float*)d_in[4]; ar0 = (const float*)d_in[5];
        b0  = (const float*)d_in[6];  W1  = (const float*)d_in[7]; al1 = (const float*)d_in[8];
        ar1 = (const float*)d_in[9];  b1  = (const float*)d_in[10];
    }
    float* out = (float*)d_out;

    float *h0, *h1, *h1p, *el0, *er0, *el1, *er1;
    cudaGetSymbolAddress((void**)&h0,  g_h0);
    cudaGetSymbolAddress((void**)&h1,  g_h1);
    cudaGetSymbolAddress((void**)&h1p, g_h1p);
    cudaGetSymbolAddress((void**)&el0, g_el0);
    cudaGetSymbolAddress((void**)&er0, g_er0);
    cudaGetSymbolAddress((void**)&el1, g_el1);
    cudaGetSymbolAddress((void**)&er1, g_er1);

    const int N = [&]{
        for (int i = 0; i < n_in; ++i) if (in_sizes[i] % D_IN == 0 && in_sizes[i] > 1000000) return in_sizes[i] / D_IN;
        return MAXN; }();
    int E = MAXE;
    for (int i = 0; i < n_in; ++i) if ((const void*)d_in[i] == (const void*)src) { E = in_sizes[i]; break; }

    cudaFuncSetAttribute(gemm0_mma_kernel, cudaFuncAttributeMaxDynamicSharedMemorySize, SM_BYTES);

    const int TB = 256;
    const int nwarp_blocks = (N + 7) / 8;
    const int nch = (N + 1023) / 1024;

    // Launch order chosen so gemm0_mma is capture slot 5 for ncu -s 5 -c 1.
    prep_b_kernel<<<(NPAD * KPAD + 255) / 256, 256>>>(W0);              // 0
    zero_deg_kernel<<<(N + TB - 1) / TB, TB>>>(N);                      // 1
    count_kernel<<<(E + TB - 1) / TB, TB>>>(dst, E);                    // 2
    scan_chunk_sums_kernel<<<nch, TB>>>(N);                             // 3
    scan_partials_kernel<<<1, 32>>>(nch, N, E);                         // 4
    gemm0_mma_kernel<<<(N + 127) / 128, 256, SM_BYTES>>>(X, N);         // 5 <- ncu
    scan_final_kernel<<<nch, TB>>>(N);                                  // 6
    fill_kernel<<<(E + TB - 1) / TB, TB>>>(src, dst, E);                // 7
    elr_kernel<<<nwarp_blocks, TB>>>(h0, al0, ar0, el0, er0, N);        // 8
    aggregate_kernel<D_H, 5><<<nwarp_blocks, TB>>>(h0, el0, er0, b0, h1, N);   // 9
    proj1_kernel<<<nwarp_blocks, TB>>>(h1, W1, al1, ar1, h1p, el1, er1, N);    // 10
    aggregate_kernel<D_O, 1><<<nwarp_blocks, TB>>>(h1p, el1, er1, b1, out, N); // 11
}